// round 14
// baseline (speedup 1.0000x reference)
#include <cuda_runtime.h>
#include <cuda_fp16.h>
#include <cstdint>

#define D     256
#define MAXN  50000
#define NPAD  50048
#define MAXE  800000

// ---------------- scratch (no allocations allowed) ----------------
__device__ __align__(16) __half g_Bth[2][256 * 512];     // B per layer, [s][n][16]
// A fp16 planes, staged [s<16][row][16] (dense, NPAD rows)
__device__ __align__(16) __half g_AGh[(size_t)16 * NPAD * 16];  // agg
__device__ __align__(16) __half g_Xh [(size_t)16 * NPAD * 16];  // x
__device__ __align__(16) __half g_Hh [(size_t)16 * NPAD * 16];  // h
__device__ int g_cnt[MAXN];
__device__ int g_off[MAXN];
__device__ int g_pos[MAXN];
__device__ int g_bsum[256];       // per-block scan partials
__device__ int g_csr_src[MAXE];
__device__ int g_src[MAXE];
__device__ int g_tgt[MAXE];
__device__ int g_flag;            // 0 => edge dtype int64, nonzero => int32

__device__ __forceinline__ uint32_t smem_u32(const void* p) {
    uint32_t a;
    asm("{ .reg .u64 t; cvta.to.shared.u64 t, %1; cvt.u32.u64 %0, t; }"
        : "=r"(a) : "l"(p));
    return a;
}
__device__ __forceinline__ uint2 pack4(__half a, __half b, __half c, __half d) {
    uint2 r;
    r.x = (uint32_t)__half_as_ushort(a) | ((uint32_t)__half_as_ushort(b) << 16);
    r.y = (uint32_t)__half_as_ushort(c) | ((uint32_t)__half_as_ushort(d) << 16);
    return r;
}
__device__ __forceinline__ uint4 pack8(const __half* h) {
    uint4 r;
    r.x = (uint32_t)__half_as_ushort(h[0]) | ((uint32_t)__half_as_ushort(h[1]) << 16);
    r.y = (uint32_t)__half_as_ushort(h[2]) | ((uint32_t)__half_as_ushort(h[3]) << 16);
    r.z = (uint32_t)__half_as_ushort(h[4]) | ((uint32_t)__half_as_ushort(h[5]) << 16);
    r.w = (uint32_t)__half_as_ushort(h[6]) | ((uint32_t)__half_as_ushort(h[7]) << 16);
    return r;
}
__device__ __forceinline__ void add4(float* a, uint2 v) {
    float2 f;
    f = __half22float2(*(__half2*)&v.x); a[0] += f.x; a[1] += f.y;
    f = __half22float2(*(__half2*)&v.y); a[2] += f.x; a[3] += f.y;
}

// ---------------- init: zero counts + dtype detect (block 0) ----------------
__global__ void zero_detect_kernel(int n, const int* __restrict__ raw,
                                   int n_edges) {
    int i = blockIdx.x * blockDim.x + threadIdx.x;
    if (i < n) g_cnt[i] = 0;
    if (blockIdx.x == 0) {
        __shared__ int any;
        if (threadIdx.x == 0) any = 0;
        __syncthreads();
        int checks = min(n_edges, 4096);
        int local = 0;
        for (int e = threadIdx.x; e < checks; e += blockDim.x)
            if (raw[2 * e + 1] != 0) { local = 1; break; }
        if (local) atomicOr(&any, 1);
        __syncthreads();
        if (threadIdx.x == 0) g_flag = any;
    }
}

// ---------------- decode + in-degree count (fused) ----------------
__global__ void extract_count_kernel(const int* __restrict__ raw,
                                     int n_edges, int n_nodes) {
    int e = blockIdx.x * blockDim.x + threadIdx.x;
    if (e >= n_edges) return;
    int s, t;
    if (g_flag == 0) {             // int64 layout: low word of each int64
        s = raw[2 * e];
        t = raw[2 * (n_edges + e)];
    } else {                       // int32 layout
        s = raw[e];
        t = raw[n_edges + e];
    }
    s = min(max(s, 0), n_nodes - 1);
    t = min(max(t, 0), n_nodes - 1);
    g_src[e] = s;
    g_tgt[e] = t;
    atomicAdd(&g_cnt[t], 1);
}

// ---------------- parallel 3-phase scan of g_cnt -> g_off, g_pos -----------
__global__ void scan_a_kernel(int n) {
    __shared__ int sh[256];
    int tid = threadIdx.x;
    int i = blockIdx.x * 256 + tid;
    int v = (i < n) ? g_cnt[i] : 0;
    sh[tid] = v;
    __syncthreads();
    #pragma unroll
    for (int off = 1; off < 256; off <<= 1) {
        int t = (tid >= off) ? sh[tid - off] : 0;
        __syncthreads();
        sh[tid] += t;
        __syncthreads();
    }
    if (i < n) g_pos[i] = sh[tid];
    if (tid == 255) g_bsum[blockIdx.x] = sh[255];
}
__global__ void scan_b_kernel(int nb) {
    __shared__ int sh[256];
    int tid = threadIdx.x;
    sh[tid] = (tid < nb) ? g_bsum[tid] : 0;
    __syncthreads();
    #pragma unroll
    for (int off = 1; off < 256; off <<= 1) {
        int t = (tid >= off) ? sh[tid - off] : 0;
        __syncthreads();
        sh[tid] += t;
        __syncthreads();
    }
    if (tid < nb) g_bsum[tid] = sh[tid];
}
__global__ void scan_c_kernel(int n) {
    int i = blockIdx.x * 256 + threadIdx.x;
    if (i >= n) return;
    int base = blockIdx.x ? g_bsum[blockIdx.x - 1] : 0;
    int off = base + g_pos[i] - g_cnt[i];
    g_off[i] = off;
    g_pos[i] = off;
}

__global__ void build_kernel(int n_edges) {
    int e = blockIdx.x * blockDim.x + threadIdx.x;
    if (e < n_edges) {
        int p = atomicAdd(&g_pos[g_tgt[e]], 1);
        g_csr_src[p] = g_src[e];
    }
}

// ---------------- one-time x -> staged fp16 plane ----------------
__global__ void convert_x_kernel(const float* __restrict__ x, int n_nodes) {
    int t = blockIdx.x * blockDim.x + threadIdx.x;
    if (t >= n_nodes * 64) return;
    int row = t >> 6;
    int g   = t & 63;                  // k0 = 4g
    float4 v = *(const float4*)(x + (size_t)row * D + g * 4);
    uint2 h = pack4(__float2half_rn(v.x), __float2half_rn(v.y),
                    __float2half_rn(v.z), __float2half_rn(v.w));
    *(uint2*)(g_Xh + ((size_t)(g >> 2) * NPAD + row) * 16 + (g & 3) * 4) = h;
}

// ---------------- W prep (both layers): [Wl;Wr]^T -> staged [s][n][16] -----
__global__ void prep_w_kernel(const float* __restrict__ W1l,
                              const float* __restrict__ W1r,
                              const float* __restrict__ W2l,
                              const float* __restrict__ W2r) {
    int tid = blockIdx.x * blockDim.x + threadIdx.x;
    if (tid >= 2 * 256 * 512) return;
    int layer = tid >> 17;
    int k = tid & 511;
    int n = (tid >> 9) & 255;
    const float* Wl = layer ? W2l : W1l;
    const float* Wr = layer ? W2r : W1r;
    float v = (k < 256) ? Wl[(size_t)k * 256 + n]
                        : Wr[(size_t)(k - 256) * 256 + n];
    g_Bth[layer][(k >> 4) * 4096 + n * 16 + (k & 15)] = __float2half_rn(v);
}

// ---------------- gather mean-aggregate over STAGED planes -----------------
// lane L covers k = 8L..8L+7 -> plane sp=L>>1, chunk offset (L&1)*8 (16B = one
// L2 sector, so gather traffic equals the row-major layout's).
__global__ void __launch_bounds__(256)
aggregate16_kernel(const __half* __restrict__ featst, int n_nodes,
                   __half* __restrict__ outh) {
    int warp = (blockIdx.x * blockDim.x + threadIdx.x) >> 5;
    int lane = threadIdx.x & 31;
    if (warp >= n_nodes) return;

    int beg = g_off[warp];
    int deg = g_cnt[warp];

    const __half* base = featst + ((size_t)(lane >> 1) * NPAD) * 16
                       + (lane & 1) * 8;

    float acc[8] = {0.f, 0.f, 0.f, 0.f, 0.f, 0.f, 0.f, 0.f};
    int i = 0;
    for (; i + 4 <= deg; i += 4) {
        int s0 = __ldg(&g_csr_src[beg + i]);
        int s1 = __ldg(&g_csr_src[beg + i + 1]);
        int s2 = __ldg(&g_csr_src[beg + i + 2]);
        int s3 = __ldg(&g_csr_src[beg + i + 3]);
        uint4 v0 = *(const uint4*)(base + (size_t)s0 * 16);
        uint4 v1 = *(const uint4*)(base + (size_t)s1 * 16);
        uint4 v2 = *(const uint4*)(base + (size_t)s2 * 16);
        uint4 v3 = *(const uint4*)(base + (size_t)s3 * 16);
        add4(acc, make_uint2(v0.x, v0.y)); add4(acc + 4, make_uint2(v0.z, v0.w));
        add4(acc, make_uint2(v1.x, v1.y)); add4(acc + 4, make_uint2(v1.z, v1.w));
        add4(acc, make_uint2(v2.x, v2.y)); add4(acc + 4, make_uint2(v2.z, v2.w));
        add4(acc, make_uint2(v3.x, v3.y)); add4(acc + 4, make_uint2(v3.z, v3.w));
    }
    for (; i < deg; i++) {
        int s0 = __ldg(&g_csr_src[beg + i]);
        uint4 v0 = *(const uint4*)(base + (size_t)s0 * 16);
        add4(acc, make_uint2(v0.x, v0.y)); add4(acc + 4, make_uint2(v0.z, v0.w));
    }

    float iv = 1.0f / (float)(deg > 1 ? deg : 1);
    __half h[8];
    #pragma unroll
    for (int j = 0; j < 8; j++) h[j] = __float2half_rn(acc[j] * iv);

    *(uint4*)(outh + ((size_t)(lane >> 1) * NPAD + warp) * 16
              + (lane & 1) * 8) = pack8(h);
}

// ---------------- mma.sync fp16 GEMM (1 pass, fp32 accum, BK=32) -----------
// CTA 128x256, K=512, 16 stages BK=32, 512 thr = 16 warps (4x4), warp 32x64.
// Stage smem: A 128x80B (10240) + B 256x80B (20480) = 30720B, x2 buffers.
#define ROWB   80
#define BOFF0  10240
#define STAGE_B 30720

#define LDSM4(r, addr)                                                      \
    asm volatile("ldmatrix.sync.aligned.m8n8.x4.shared.b16 "                \
                 "{%0,%1,%2,%3}, [%4];"                                     \
                 : "=r"((r)[0]), "=r"((r)[1]), "=r"((r)[2]), "=r"((r)[3])   \
                 : "r"(addr))

#define MMA16(cc, a, b0, b1)                                                \
    asm volatile("mma.sync.aligned.m16n8k16.row.col.f32.f16.f16.f32 "       \
                 "{%0,%1,%2,%3},{%4,%5,%6,%7},{%8,%9},{%0,%1,%2,%3};"       \
                 : "+f"((cc)[0]), "+f"((cc)[1]), "+f"((cc)[2]), "+f"((cc)[3]) \
                 : "r"((a)[0]), "r"((a)[1]), "r"((a)[2]), "r"((a)[3]),      \
                   "r"(b0), "r"(b1))

__global__ void __launch_bounds__(512, 1)
sage_mma_kernel(const __half* __restrict__ inh, const __half* __restrict__ Bw,
                const float* __restrict__ bias, float* __restrict__ outf,
                __half* __restrict__ hh, int n_nodes, int do_relu) {
    extern __shared__ __align__(1024) char sm[];
    const uint32_t smb = smem_u32(sm);
    const int tid  = threadIdx.x;
    const int lane = tid & 31;
    const int wid  = tid >> 5;
    const int wm   = wid & 3;
    const int wn   = wid >> 2;
    const int row0 = blockIdx.x * 128;

    // staging: threads 0..255 stage 32B of A; all 512 stage 32B of B
    const bool hasA  = tid < 256;
    const int  rowA  = (tid & 255) >> 1;
    const int  halfA = tid & 1;
    const int  nB    = tid >> 1;           // 0..255
    const int  halfB = tid & 1;
    const uint32_t aDst = rowA * ROWB + halfA * 16u;       // +32 for plane 2s+1
    const uint32_t bDst = BOFF0 + nB * ROWB + halfB * 16u; // +32 for plane 2s+1

    // ldmatrix lane addressing (80B rows; 5r mod 8 -> conflict-free)
    const uint32_t aOff = (uint32_t)(wm * 32 + (lane & 7) + 8 * ((lane >> 3) & 1)) * ROWB
                        + (((uint32_t)lane >> 4) << 4);
    const uint32_t bOff = (uint32_t)(wn * 64 + ((lane >> 4) << 3) + (lane & 7)) * ROWB
                        + ((((uint32_t)lane >> 3) & 1) << 4);

    float c[2][8][4];
    #pragma unroll
    for (int t = 0; t < 2; t++)
        #pragma unroll
        for (int nt = 0; nt < 8; nt++)
            #pragma unroll
            for (int j = 0; j < 4; j++) c[t][nt][j] = 0.f;

    uint4 ra0, ra1, rb0, rb1;
    auto ldg = [&](int s) {                 // s = 0..15, covers k-planes 2s, 2s+1
        const int p0 = 2 * s;
        if (hasA) {
            const __half* srcA = (p0 < 16) ? g_AGh : inh;
            const int pp = p0 & 15;
            const __half* pa = srcA + ((size_t)pp * NPAD + row0 + rowA) * 16
                             + halfA * 8;
            ra0 = *(const uint4*)(pa);
            ra1 = *(const uint4*)(pa + (size_t)NPAD * 16);
        }
        const __half* pb = Bw + p0 * 4096 + nB * 16 + halfB * 8;
        rb0 = *(const uint4*)(pb);
        rb1 = *(const uint4*)(pb + 4096);
    };
    auto sts = [&](int buf) {
        char* bb = sm + buf * STAGE_B;
        if (hasA) {
            *(uint4*)(bb + aDst)      = ra0;
            *(uint4*)(bb + aDst + 32) = ra1;
        }
        *(uint4*)(bb + bDst)      = rb0;
        *(uint4*)(bb + bDst + 32) = rb1;
    };
    auto compute = [&](int buf) {
        const uint32_t bb = smb + buf * STAGE_B;
        #pragma unroll
        for (int ks = 0; ks < 2; ks++) {
            const uint32_t ko = ks * 32;
            uint32_t ah[2][4];
            LDSM4(ah[0], bb + aOff + ko);
            LDSM4(ah[1], bb + aOff + 1280 + ko);
            #pragma unroll
            for (int nt2 = 0; nt2 < 4; nt2++) {
                uint32_t bh[4];
                LDSM4(bh, bb + BOFF0 + bOff + nt2 * 1280 + ko);
                #pragma unroll
                for (int t = 0; t < 2; t++) {
                    MMA16(c[t][nt2 * 2],     ah[t], bh[0], bh[1]);
                    MMA16(c[t][nt2 * 2 + 1], ah[t], bh[2], bh[3]);
                }
            }
        }
    };

    // prologue
    ldg(0);
    sts(0);
    ldg(1);
    __syncthreads();

    #pragma unroll 1
    for (int s = 0; s < 16; s++) {
        compute(s & 1);
        if (s + 1 < 16) {
            sts((s + 1) & 1);          // write buffer not being read
            if (s + 2 < 16) ldg(s + 2);
        }
        __syncthreads();
    }

    // ---- epilogue ----
    #pragma unroll
    for (int t = 0; t < 2; t++) {
        const int r1 = row0 + wm * 32 + t * 16 + (lane >> 2);
        #pragma unroll
        for (int nt = 0; nt < 8; nt++) {
            const int col = wn * 64 + nt * 8 + 2 * (lane & 3);
            float2 b2 = *(const float2*)(bias + col);
            float v0 = c[t][nt][0] + b2.x;
            float v1 = c[t][nt][1] + b2.y;
            float v2 = c[t][nt][2] + b2.x;
            float v3 = c[t][nt][3] + b2.y;
            if (do_relu) {
                v0 = fmaxf(v0, 0.f); v1 = fmaxf(v1, 0.f);
                v2 = fmaxf(v2, 0.f); v3 = fmaxf(v3, 0.f);
            }
            const int sp = col >> 4, kk = col & 15;
            if (r1 < n_nodes) {
                if (outf)
                    *(float2*)(outf + (size_t)r1 * D + col) = make_float2(v0, v1);
                else
                    *(uint32_t*)(hh + ((size_t)sp * NPAD + r1) * 16 + kk) =
                        (uint32_t)__half_as_ushort(__float2half_rn(v0)) |
                        ((uint32_t)__half_as_ushort(__float2half_rn(v1)) << 16);
            }
            if (r1 + 8 < n_nodes) {
                if (outf)
                    *(float2*)(outf + (size_t)(r1 + 8) * D + col) = make_float2(v2, v3);
                else
                    *(uint32_t*)(hh + ((size_t)sp * NPAD + r1 + 8) * 16 + kk) =
                        (uint32_t)__half_as_ushort(__float2half_rn(v2)) |
                        ((uint32_t)__half_as_ushort(__float2half_rn(v3)) << 16);
            }
        }
    }
}

// ---------------- launch ----------------
extern "C" void kernel_launch(void* const* d_in, const int* in_sizes, int n_in,
                              void* d_out, int out_size) {
    const float* x   = (const float*)d_in[0];
    const int*   raw = (const int*)d_in[1];
    const float* W1l = (const float*)d_in[2];
    const float* b1  = (const float*)d_in[3];
    const float* W1r = (const float*)d_in[4];
    const float* W2l = (const float*)d_in[5];
    const float* b2  = (const float*)d_in[6];
    const float* W2r = (const float*)d_in[7];
    float* out = (float*)d_out;

    const int n_nodes = in_sizes[0] / D;
    const int n_edges = in_sizes[1] / 2;

    __half *xh, *hhp, *agh, *bw;
    cudaGetSymbolAddress((void**)&xh,  g_Xh);
    cudaGetSymbolAddress((void**)&hhp, g_Hh);
    cudaGetSymbolAddress((void**)&agh, g_AGh);
    cudaGetSymbolAddress((void**)&bw,  g_Bth);

    cudaFuncSetAttribute(sage_mma_kernel,
                         cudaFuncAttributeMaxDynamicSharedMemorySize,
                         2 * STAGE_B);

    const int mma_blocks  = (n_nodes + 127) / 128;
    const int agg_blocks  = (n_nodes * 32 + 255) / 256;
    const int eb = (n_edges + 255) / 256;
    const int nb = (n_nodes + 255) / 256;
    const int scan_blocks = (n_nodes + 255) / 256;
    const int wb = (2 * 256 * 512 + 255) / 256;
    const int cb = (n_nodes * 64 + 255) / 256;
    const int smem = 2 * STAGE_B;

    // ---- decode + CSR build ----
    zero_detect_kernel<<<nb, 256>>>(n_nodes, raw, n_edges);
    extract_count_kernel<<<eb, 256>>>(raw, n_edges, n_nodes);
    scan_a_kernel<<<scan_blocks, 256>>>(n_nodes);
    scan_b_kernel<<<1, 256>>>(scan_blocks);
    scan_c_kernel<<<scan_blocks, 256>>>(n_nodes);
    build_kernel<<<eb, 256>>>(n_edges);

    // ---- one-time conversions ----
    convert_x_kernel<<<cb, 256>>>(x, n_nodes);
    prep_w_kernel<<<wb, 256>>>(W1l, W1r, W2l, W2r);

    // ---- layer 1 ----
    aggregate16_kernel<<<agg_blocks, 256>>>(xh, n_nodes, agh);
    sage_mma_kernel<<<mma_blocks, 512, smem>>>(xh, bw, b1, nullptr,
                                               hhp, n_nodes, 1);

    // ---- layer 2 ----
    aggregate16_kernel<<<agg_blocks, 256>>>(hhp, n_nodes, agh);
    sage_mma_kernel<<<mma_blocks, 512, smem>>>(hhp, bw + 256 * 512, b2, out,
                                               nullptr, n_nodes, 0);
}

// round 15
// speedup vs baseline: 1.1796x; 1.1796x over previous
#include <cuda_runtime.h>
#include <cuda_fp16.h>
#include <cstdint>

#define D     256
#define MAXN  50000
#define NPAD  50048
#define MAXE  800000

// ---------------- scratch (no allocations allowed) ----------------
__device__ __align__(16) __half g_Bth[2][256 * 512];     // B per layer, [s][n][16]
// A fp16 planes, staged [s<16][row][16] (dense, NPAD rows)
__device__ __align__(16) __half g_AGh[(size_t)16 * NPAD * 16];  // agg
__device__ __align__(16) __half g_Xh [(size_t)16 * NPAD * 16];  // x
__device__ __align__(16) __half g_Hh [(size_t)16 * NPAD * 16];  // h
// fp16 row-major feature copies for the gather (512B contiguous rows)
__device__ __align__(16) __half g_X16[(size_t)MAXN * D];
__device__ __align__(16) __half g_H16[(size_t)MAXN * D];
__device__ int g_cnt[MAXN];
__device__ int g_off[MAXN];
__device__ int g_pos[MAXN];
__device__ int g_bsum[256];       // per-block scan partials
__device__ int g_csr_src[MAXE];
__device__ int g_src[MAXE];
__device__ int g_tgt[MAXE];
__device__ int g_flag;            // 0 => edge dtype int64, nonzero => int32

__device__ __forceinline__ uint32_t smem_u32(const void* p) {
    uint32_t a;
    asm("{ .reg .u64 t; cvta.to.shared.u64 t, %1; cvt.u32.u64 %0, t; }"
        : "=r"(a) : "l"(p));
    return a;
}
__device__ __forceinline__ uint2 pack4(__half a, __half b, __half c, __half d) {
    uint2 r;
    r.x = (uint32_t)__half_as_ushort(a) | ((uint32_t)__half_as_ushort(b) << 16);
    r.y = (uint32_t)__half_as_ushort(c) | ((uint32_t)__half_as_ushort(d) << 16);
    return r;
}
__device__ __forceinline__ uint4 pack8(const __half* h) {
    uint4 r;
    r.x = (uint32_t)__half_as_ushort(h[0]) | ((uint32_t)__half_as_ushort(h[1]) << 16);
    r.y = (uint32_t)__half_as_ushort(h[2]) | ((uint32_t)__half_as_ushort(h[3]) << 16);
    r.z = (uint32_t)__half_as_ushort(h[4]) | ((uint32_t)__half_as_ushort(h[5]) << 16);
    r.w = (uint32_t)__half_as_ushort(h[6]) | ((uint32_t)__half_as_ushort(h[7]) << 16);
    return r;
}
__device__ __forceinline__ void add8(float* a, uint4 v) {
    float2 f;
    f = __half22float2(*(__half2*)&v.x); a[0] += f.x; a[1] += f.y;
    f = __half22float2(*(__half2*)&v.y); a[2] += f.x; a[3] += f.y;
    f = __half22float2(*(__half2*)&v.z); a[4] += f.x; a[5] += f.y;
    f = __half22float2(*(__half2*)&v.w); a[6] += f.x; a[7] += f.y;
}

// ---------------- init: zero counts + dtype detect (block 0) ----------------
__global__ void zero_detect_kernel(int n, const int* __restrict__ raw,
                                   int n_edges) {
    int i = blockIdx.x * blockDim.x + threadIdx.x;
    if (i < n) g_cnt[i] = 0;
    if (blockIdx.x == 0) {
        __shared__ int any;
        if (threadIdx.x == 0) any = 0;
        __syncthreads();
        int checks = min(n_edges, 4096);
        int local = 0;
        for (int e = threadIdx.x; e < checks; e += blockDim.x)
            if (raw[2 * e + 1] != 0) { local = 1; break; }
        if (local) atomicOr(&any, 1);
        __syncthreads();
        if (threadIdx.x == 0) g_flag = any;
    }
}

// ---------------- decode + in-degree count (fused) ----------------
__global__ void extract_count_kernel(const int* __restrict__ raw,
                                     int n_edges, int n_nodes) {
    int e = blockIdx.x * blockDim.x + threadIdx.x;
    if (e >= n_edges) return;
    int s, t;
    if (g_flag == 0) {             // int64 layout: low word of each int64
        s = raw[2 * e];
        t = raw[2 * (n_edges + e)];
    } else {                       // int32 layout
        s = raw[e];
        t = raw[n_edges + e];
    }
    s = min(max(s, 0), n_nodes - 1);
    t = min(max(t, 0), n_nodes - 1);
    g_src[e] = s;
    g_tgt[e] = t;
    atomicAdd(&g_cnt[t], 1);
}

// ---------------- parallel 3-phase scan of g_cnt -> g_off, g_pos -----------
__global__ void scan_a_kernel(int n) {
    __shared__ int sh[256];
    int tid = threadIdx.x;
    int i = blockIdx.x * 256 + tid;
    int v = (i < n) ? g_cnt[i] : 0;
    sh[tid] = v;
    __syncthreads();
    #pragma unroll
    for (int off = 1; off < 256; off <<= 1) {
        int t = (tid >= off) ? sh[tid - off] : 0;
        __syncthreads();
        sh[tid] += t;
        __syncthreads();
    }
    if (i < n) g_pos[i] = sh[tid];
    if (tid == 255) g_bsum[blockIdx.x] = sh[255];
}
__global__ void scan_b_kernel(int nb) {
    __shared__ int sh[256];
    int tid = threadIdx.x;
    sh[tid] = (tid < nb) ? g_bsum[tid] : 0;
    __syncthreads();
    #pragma unroll
    for (int off = 1; off < 256; off <<= 1) {
        int t = (tid >= off) ? sh[tid - off] : 0;
        __syncthreads();
        sh[tid] += t;
        __syncthreads();
    }
    if (tid < nb) g_bsum[tid] = sh[tid];
}
__global__ void scan_c_kernel(int n) {
    int i = blockIdx.x * 256 + threadIdx.x;
    if (i >= n) return;
    int base = blockIdx.x ? g_bsum[blockIdx.x - 1] : 0;
    int off = base + g_pos[i] - g_cnt[i];
    g_off[i] = off;
    g_pos[i] = off;
}

__global__ void build_kernel(int n_edges) {
    int e = blockIdx.x * blockDim.x + threadIdx.x;
    if (e < n_edges) {
        int p = atomicAdd(&g_pos[g_tgt[e]], 1);
        g_csr_src[p] = g_src[e];
    }
}

// ---------------- one-time x -> fp16 row copy + staged plane ----------------
__global__ void convert_x_kernel(const float* __restrict__ x, int n_nodes) {
    int t = blockIdx.x * blockDim.x + threadIdx.x;
    if (t >= n_nodes * 64) return;
    int row = t >> 6;
    int g   = t & 63;                  // k0 = 4g
    float4 v = *(const float4*)(x + (size_t)row * D + g * 4);
    uint2 h = pack4(__float2half_rn(v.x), __float2half_rn(v.y),
                    __float2half_rn(v.z), __float2half_rn(v.w));
    *(uint2*)(g_Xh + ((size_t)(g >> 2) * NPAD + row) * 16 + (g & 3) * 4) = h;
    *(uint2*)(g_X16 + (size_t)row * D + g * 4) = h;
}

// ---------------- W prep (both layers): [Wl;Wr]^T -> staged [s][n][16] -----
__global__ void prep_w_kernel(const float* __restrict__ W1l,
                              const float* __restrict__ W1r,
                              const float* __restrict__ W2l,
                              const float* __restrict__ W2r) {
    int tid = blockIdx.x * blockDim.x + threadIdx.x;
    if (tid >= 2 * 256 * 512) return;
    int layer = tid >> 17;
    int k = tid & 511;
    int n = (tid >> 9) & 255;
    const float* Wl = layer ? W2l : W1l;
    const float* Wr = layer ? W2r : W1r;
    float v = (k < 256) ? Wl[(size_t)k * 256 + n]
                        : Wr[(size_t)(k - 256) * 256 + n];
    g_Bth[layer][(k >> 4) * 4096 + n * 16 + (k & 15)] = __float2half_rn(v);
}

// ---------------- gather mean-aggregate over fp16 rows (512B contiguous) ---
__global__ void __launch_bounds__(256)
aggregate16_kernel(const __half* __restrict__ feat, int n_nodes,
                   __half* __restrict__ outh) {
    int warp = (blockIdx.x * blockDim.x + threadIdx.x) >> 5;
    int lane = threadIdx.x & 31;
    if (warp >= n_nodes) return;

    int beg = g_off[warp];
    int deg = g_cnt[warp];

    float acc[8] = {0.f, 0.f, 0.f, 0.f, 0.f, 0.f, 0.f, 0.f};
    int i = 0;
    for (; i + 4 <= deg; i += 4) {
        int s0 = __ldg(&g_csr_src[beg + i]);
        int s1 = __ldg(&g_csr_src[beg + i + 1]);
        int s2 = __ldg(&g_csr_src[beg + i + 2]);
        int s3 = __ldg(&g_csr_src[beg + i + 3]);
        uint4 v0 = *(const uint4*)(feat + (size_t)s0 * D + lane * 8);
        uint4 v1 = *(const uint4*)(feat + (size_t)s1 * D + lane * 8);
        uint4 v2 = *(const uint4*)(feat + (size_t)s2 * D + lane * 8);
        uint4 v3 = *(const uint4*)(feat + (size_t)s3 * D + lane * 8);
        add8(acc, v0); add8(acc, v1); add8(acc, v2); add8(acc, v3);
    }
    for (; i < deg; i++) {
        int s0 = __ldg(&g_csr_src[beg + i]);
        uint4 v0 = *(const uint4*)(feat + (size_t)s0 * D + lane * 8);
        add8(acc, v0);
    }

    float iv = 1.0f / (float)(deg > 1 ? deg : 1);
    __half h[8];
    #pragma unroll
    for (int j = 0; j < 8; j++) h[j] = __float2half_rn(acc[j] * iv);

    const int sp = lane >> 1;
    const int kk = (lane & 1) * 8;
    *(uint4*)(outh + ((size_t)sp * NPAD + warp) * 16 + kk) = pack8(h);
}

// ---------------- mma.sync fp16 GEMM (1 pass, fp32 accum, BK=32) -----------
// CTA 128x256, K=512, 16 stages BK=32, 512 thr = 16 warps (4x4), warp 32x64.
// Stage smem: A 128x80B (10240) + B 256x80B (20480) = 30720B, x2 buffers.
#define ROWB   80
#define BOFF0  10240
#define STAGE_B 30720

#define LDSM4(r, addr)                                                      \
    asm volatile("ldmatrix.sync.aligned.m8n8.x4.shared.b16 "                \
                 "{%0,%1,%2,%3}, [%4];"                                     \
                 : "=r"((r)[0]), "=r"((r)[1]), "=r"((r)[2]), "=r"((r)[3])   \
                 : "r"(addr))

#define MMA16(cc, a, b0, b1)                                                \
    asm volatile("mma.sync.aligned.m16n8k16.row.col.f32.f16.f16.f32 "       \
                 "{%0,%1,%2,%3},{%4,%5,%6,%7},{%8,%9},{%0,%1,%2,%3};"       \
                 : "+f"((cc)[0]), "+f"((cc)[1]), "+f"((cc)[2]), "+f"((cc)[3]) \
                 : "r"((a)[0]), "r"((a)[1]), "r"((a)[2]), "r"((a)[3]),      \
                   "r"(b0), "r"(b1))

__global__ void __launch_bounds__(512, 1)
sage_mma_kernel(const __half* __restrict__ inh, const __half* __restrict__ Bw,
                const float* __restrict__ bias, float* __restrict__ outf,
                __half* __restrict__ hh, __half* __restrict__ h16,
                int n_nodes, int do_relu) {
    extern __shared__ __align__(1024) char sm[];
    const uint32_t smb = smem_u32(sm);
    const int tid  = threadIdx.x;
    const int lane = tid & 31;
    const int wid  = tid >> 5;
    const int wm   = wid & 3;
    const int wn   = wid >> 2;
    const int row0 = blockIdx.x * 128;

    // staging: threads 0..255 stage 32B of A; all 512 stage 32B of B
    const bool hasA  = tid < 256;
    const int  rowA  = (tid & 255) >> 1;
    const int  halfA = tid & 1;
    const int  nB    = tid >> 1;           // 0..255
    const int  halfB = tid & 1;
    const uint32_t aDst = rowA * ROWB + halfA * 16u;       // +32 for plane 2s+1
    const uint32_t bDst = BOFF0 + nB * ROWB + halfB * 16u; // +32 for plane 2s+1

    // ldmatrix lane addressing (80B rows; 5r mod 8 -> conflict-free)
    const uint32_t aOff = (uint32_t)(wm * 32 + (lane & 7) + 8 * ((lane >> 3) & 1)) * ROWB
                        + (((uint32_t)lane >> 4) << 4);
    const uint32_t bOff = (uint32_t)(wn * 64 + ((lane >> 4) << 3) + (lane & 7)) * ROWB
                        + ((((uint32_t)lane >> 3) & 1) << 4);

    float c[2][8][4];
    #pragma unroll
    for (int t = 0; t < 2; t++)
        #pragma unroll
        for (int nt = 0; nt < 8; nt++)
            #pragma unroll
            for (int j = 0; j < 4; j++) c[t][nt][j] = 0.f;

    uint4 ra0, ra1, rb0, rb1;
    auto ldg = [&](int s) {                 // s = 0..15, covers k-planes 2s, 2s+1
        const int p0 = 2 * s;
        if (hasA) {
            const __half* srcA = (p0 < 16) ? g_AGh : inh;
            const int pp = p0 & 15;
            const __half* pa = srcA + ((size_t)pp * NPAD + row0 + rowA) * 16
                             + halfA * 8;
            ra0 = *(const uint4*)(pa);
            ra1 = *(const uint4*)(pa + (size_t)NPAD * 16);
        }
        const __half* pb = Bw + p0 * 4096 + nB * 16 + halfB * 8;
        rb0 = *(const uint4*)(pb);
        rb1 = *(const uint4*)(pb + 4096);
    };
    auto sts = [&](int buf) {
        char* bb = sm + buf * STAGE_B;
        if (hasA) {
            *(uint4*)(bb + aDst)      = ra0;
            *(uint4*)(bb + aDst + 32) = ra1;
        }
        *(uint4*)(bb + bDst)      = rb0;
        *(uint4*)(bb + bDst + 32) = rb1;
    };
    auto compute = [&](int buf) {
        const uint32_t bb = smb + buf * STAGE_B;
        #pragma unroll
        for (int ks = 0; ks < 2; ks++) {
            const uint32_t ko = ks * 32;
            uint32_t ah[2][4];
            LDSM4(ah[0], bb + aOff + ko);
            LDSM4(ah[1], bb + aOff + 1280 + ko);
            #pragma unroll
            for (int nt2 = 0; nt2 < 4; nt2++) {
                uint32_t bh[4];
                LDSM4(bh, bb + BOFF0 + bOff + nt2 * 1280 + ko);
                #pragma unroll
                for (int t = 0; t < 2; t++) {
                    MMA16(c[t][nt2 * 2],     ah[t], bh[0], bh[1]);
                    MMA16(c[t][nt2 * 2 + 1], ah[t], bh[2], bh[3]);
                }
            }
        }
    };

    // prologue
    ldg(0);
    sts(0);
    ldg(1);
    __syncthreads();

    #pragma unroll 1
    for (int s = 0; s < 16; s++) {
        compute(s & 1);
        if (s + 1 < 16) {
            sts((s + 1) & 1);          // write buffer not being read
            if (s + 2 < 16) ldg(s + 2);
        }
        __syncthreads();
    }

    // ---- epilogue ----
    #pragma unroll
    for (int t = 0; t < 2; t++) {
        const int r1 = row0 + wm * 32 + t * 16 + (lane >> 2);
        #pragma unroll
        for (int nt = 0; nt < 8; nt++) {
            const int col = wn * 64 + nt * 8 + 2 * (lane & 3);
            float2 b2 = *(const float2*)(bias + col);
            float v0 = c[t][nt][0] + b2.x;
            float v1 = c[t][nt][1] + b2.y;
            float v2 = c[t][nt][2] + b2.x;
            float v3 = c[t][nt][3] + b2.y;
            if (do_relu) {
                v0 = fmaxf(v0, 0.f); v1 = fmaxf(v1, 0.f);
                v2 = fmaxf(v2, 0.f); v3 = fmaxf(v3, 0.f);
            }
            const int sp = col >> 4, kk = col & 15;
            if (r1 < n_nodes) {
                if (outf)
                    *(float2*)(outf + (size_t)r1 * D + col) = make_float2(v0, v1);
                else {
                    uint32_t hi2 =
                        (uint32_t)__half_as_ushort(__float2half_rn(v0)) |
                        ((uint32_t)__half_as_ushort(__float2half_rn(v1)) << 16);
                    *(uint32_t*)(hh + ((size_t)sp * NPAD + r1) * 16 + kk) = hi2;
                    *(uint32_t*)(h16 + (size_t)r1 * D + col) = hi2;
                }
            }
            if (r1 + 8 < n_nodes) {
                if (outf)
                    *(float2*)(outf + (size_t)(r1 + 8) * D + col) = make_float2(v2, v3);
                else {
                    uint32_t hi2 =
                        (uint32_t)__half_as_ushort(__float2half_rn(v2)) |
                        ((uint32_t)__half_as_ushort(__float2half_rn(v3)) << 16);
                    *(uint32_t*)(hh + ((size_t)sp * NPAD + r1 + 8) * 16 + kk) = hi2;
                    *(uint32_t*)(h16 + (size_t)(r1 + 8) * D + col) = hi2;
                }
            }
        }
    }
}

// ---------------- launch ----------------
extern "C" void kernel_launch(void* const* d_in, const int* in_sizes, int n_in,
                              void* d_out, int out_size) {
    const float* x   = (const float*)d_in[0];
    const int*   raw = (const int*)d_in[1];
    const float* W1l = (const float*)d_in[2];
    const float* b1  = (const float*)d_in[3];
    const float* W1r = (const float*)d_in[4];
    const float* W2l = (const float*)d_in[5];
    const float* b2  = (const float*)d_in[6];
    const float* W2r = (const float*)d_in[7];
    float* out = (float*)d_out;

    const int n_nodes = in_sizes[0] / D;
    const int n_edges = in_sizes[1] / 2;

    __half *xh, *hhp, *agh, *bw, *x16, *h16;
    cudaGetSymbolAddress((void**)&xh,  g_Xh);
    cudaGetSymbolAddress((void**)&hhp, g_Hh);
    cudaGetSymbolAddress((void**)&agh, g_AGh);
    cudaGetSymbolAddress((void**)&bw,  g_Bth);
    cudaGetSymbolAddress((void**)&x16, g_X16);
    cudaGetSymbolAddress((void**)&h16, g_H16);

    cudaFuncSetAttribute(sage_mma_kernel,
                         cudaFuncAttributeMaxDynamicSharedMemorySize,
                         2 * STAGE_B);

    const int mma_blocks  = (n_nodes + 127) / 128;
    const int agg_blocks  = (n_nodes * 32 + 255) / 256;
    const int eb = (n_edges + 255) / 256;
    const int nb = (n_nodes + 255) / 256;
    const int scan_blocks = (n_nodes + 255) / 256;
    const int wb = (2 * 256 * 512 + 255) / 256;
    const int cb = (n_nodes * 64 + 255) / 256;
    const int smem = 2 * STAGE_B;

    // ---- decode + CSR build ----
    zero_detect_kernel<<<nb, 256>>>(n_nodes, raw, n_edges);
    extract_count_kernel<<<eb, 256>>>(raw, n_edges, n_nodes);
    scan_a_kernel<<<scan_blocks, 256>>>(n_nodes);
    scan_b_kernel<<<1, 256>>>(scan_blocks);
    scan_c_kernel<<<scan_blocks, 256>>>(n_nodes);
    build_kernel<<<eb, 256>>>(n_edges);

    // ---- one-time conversions ----
    convert_x_kernel<<<cb, 256>>>(x, n_nodes);
    prep_w_kernel<<<wb, 256>>>(W1l, W1r, W2l, W2r);

    // ---- layer 1 ----
    aggregate16_kernel<<<agg_blocks, 256>>>(x16, n_nodes, agh);
    sage_mma_kernel<<<mma_blocks, 512, smem>>>(xh, bw, b1, nullptr,
                                               hhp, h16, n_nodes, 1);

    // ---- layer 2 ----
    aggregate16_kernel<<<agg_blocks, 256>>>(h16, n_nodes, agh);
    sage_mma_kernel<<<mma_blocks, 512, smem>>>(hhp, bw + 256 * 512, b2, out,
                                               nullptr, nullptr, n_nodes, 0);
}

// round 16
// speedup vs baseline: 1.2214x; 1.0354x over previous
#include <cuda_runtime.h>
#include <cuda_fp16.h>
#include <cstdint>

#define D     256
#define MAXN  50000
#define NPAD  50048
#define MAXE  800000

// ---------------- scratch (no allocations allowed) ----------------
__device__ __align__(16) __half g_Bth[2][256 * 512];     // B per layer, [s][n][16]
// A fp16 planes, staged [s<16][row][16] (dense, NPAD rows)
__device__ __align__(16) __half g_AGh[(size_t)16 * NPAD * 16];  // agg
__device__ __align__(16) __half g_Xh [(size_t)16 * NPAD * 16];  // x
__device__ __align__(16) __half g_Hh [(size_t)16 * NPAD * 16];  // h
// fp16 row-major feature copies for the gather (512B contiguous rows)
__device__ __align__(16) __half g_X16[(size_t)MAXN * D];
__device__ __align__(16) __half g_H16[(size_t)MAXN * D];
__device__ int g_cnt[MAXN];
__device__ int g_off[MAXN];
__device__ int g_pos[MAXN];
__device__ int g_bsum[256];       // per-block scan partials
__device__ int g_csr_src[MAXE];
__device__ int g_src[MAXE];
__device__ int g_tgt[MAXE];
__device__ int g_flag;            // 0 => edge dtype int64, nonzero => int32

__device__ __forceinline__ uint32_t smem_u32(const void* p) {
    uint32_t a;
    asm("{ .reg .u64 t; cvta.to.shared.u64 t, %1; cvt.u32.u64 %0, t; }"
        : "=r"(a) : "l"(p));
    return a;
}
__device__ __forceinline__ uint2 pack4(__half a, __half b, __half c, __half d) {
    uint2 r;
    r.x = (uint32_t)__half_as_ushort(a) | ((uint32_t)__half_as_ushort(b) << 16);
    r.y = (uint32_t)__half_as_ushort(c) | ((uint32_t)__half_as_ushort(d) << 16);
    return r;
}
__device__ __forceinline__ uint4 pack8(const __half* h) {
    uint4 r;
    r.x = (uint32_t)__half_as_ushort(h[0]) | ((uint32_t)__half_as_ushort(h[1]) << 16);
    r.y = (uint32_t)__half_as_ushort(h[2]) | ((uint32_t)__half_as_ushort(h[3]) << 16);
    r.z = (uint32_t)__half_as_ushort(h[4]) | ((uint32_t)__half_as_ushort(h[5]) << 16);
    r.w = (uint32_t)__half_as_ushort(h[6]) | ((uint32_t)__half_as_ushort(h[7]) << 16);
    return r;
}
__device__ __forceinline__ void add8(float* a, uint4 v) {
    float2 f;
    f = __half22float2(*(__half2*)&v.x); a[0] += f.x; a[1] += f.y;
    f = __half22float2(*(__half2*)&v.y); a[2] += f.x; a[3] += f.y;
    f = __half22float2(*(__half2*)&v.z); a[4] += f.x; a[5] += f.y;
    f = __half22float2(*(__half2*)&v.w); a[6] += f.x; a[7] += f.y;
}

// ---------------- fused prologue: zero counts + detect + convert_x + prep_w
// block ranges: [0, nb) zero+detect | [nb, nb+cb) convert_x | [nb+cb, +wb) W
__global__ void prologue_kernel(int n_nodes, const int* __restrict__ raw,
                                int n_edges, const float* __restrict__ x,
                                const float* __restrict__ W1l,
                                const float* __restrict__ W1r,
                                const float* __restrict__ W2l,
                                const float* __restrict__ W2r,
                                int nb, int cb) {
    const int b = blockIdx.x;
    if (b < nb) {
        int i = b * 256 + threadIdx.x;
        if (i < n_nodes) g_cnt[i] = 0;
        if (b == 0) {
            __shared__ int any;
            if (threadIdx.x == 0) any = 0;
            __syncthreads();
            int checks = min(n_edges, 4096);
            int local = 0;
            for (int e = threadIdx.x; e < checks; e += blockDim.x)
                if (raw[2 * e + 1] != 0) { local = 1; break; }
            if (local) atomicOr(&any, 1);
            __syncthreads();
            if (threadIdx.x == 0) g_flag = any;
        }
        return;
    }
    if (b < nb + cb) {
        int t = (b - nb) * 256 + threadIdx.x;
        if (t >= n_nodes * 64) return;
        int row = t >> 6;
        int g   = t & 63;                  // k0 = 4g
        float4 v = *(const float4*)(x + (size_t)row * D + g * 4);
        uint2 h = pack4(__float2half_rn(v.x), __float2half_rn(v.y),
                        __float2half_rn(v.z), __float2half_rn(v.w));
        *(uint2*)(g_Xh + ((size_t)(g >> 2) * NPAD + row) * 16 + (g & 3) * 4) = h;
        *(uint2*)(g_X16 + (size_t)row * D + g * 4) = h;
        return;
    }
    {
        int t = (b - nb - cb) * 256 + threadIdx.x;
        if (t >= 2 * 256 * 512) return;
        int layer = t >> 17;
        int k = t & 511;
        int n = (t >> 9) & 255;
        const float* Wl = layer ? W2l : W1l;
        const float* Wr = layer ? W2r : W1r;
        float v = (k < 256) ? Wl[(size_t)k * 256 + n]
                            : Wr[(size_t)(k - 256) * 256 + n];
        g_Bth[layer][(k >> 4) * 4096 + n * 16 + (k & 15)] = __float2half_rn(v);
    }
}

// ---------------- decode + in-degree count (fused) ----------------
__global__ void extract_count_kernel(const int* __restrict__ raw,
                                     int n_edges, int n_nodes) {
    int e = blockIdx.x * blockDim.x + threadIdx.x;
    if (e >= n_edges) return;
    int s, t;
    if (g_flag == 0) {             // int64 layout: low word of each int64
        s = raw[2 * e];
        t = raw[2 * (n_edges + e)];
    } else {                       // int32 layout
        s = raw[e];
        t = raw[n_edges + e];
    }
    s = min(max(s, 0), n_nodes - 1);
    t = min(max(t, 0), n_nodes - 1);
    g_src[e] = s;
    g_tgt[e] = t;
    atomicAdd(&g_cnt[t], 1);
}

// ---------------- parallel 3-phase scan of g_cnt -> g_off, g_pos -----------
__global__ void scan_a_kernel(int n) {
    __shared__ int sh[256];
    int tid = threadIdx.x;
    int i = blockIdx.x * 256 + tid;
    int v = (i < n) ? g_cnt[i] : 0;
    sh[tid] = v;
    __syncthreads();
    #pragma unroll
    for (int off = 1; off < 256; off <<= 1) {
        int t = (tid >= off) ? sh[tid - off] : 0;
        __syncthreads();
        sh[tid] += t;
        __syncthreads();
    }
    if (i < n) g_pos[i] = sh[tid];
    if (tid == 255) g_bsum[blockIdx.x] = sh[255];
}
__global__ void scan_b_kernel(int nb) {
    __shared__ int sh[256];
    int tid = threadIdx.x;
    sh[tid] = (tid < nb) ? g_bsum[tid] : 0;
    __syncthreads();
    #pragma unroll
    for (int off = 1; off < 256; off <<= 1) {
        int t = (tid >= off) ? sh[tid - off] : 0;
        __syncthreads();
        sh[tid] += t;
        __syncthreads();
    }
    if (tid < nb) g_bsum[tid] = sh[tid];
}
__global__ void scan_c_kernel(int n) {
    int i = blockIdx.x * 256 + threadIdx.x;
    if (i >= n) return;
    int base = blockIdx.x ? g_bsum[blockIdx.x - 1] : 0;
    int off = base + g_pos[i] - g_cnt[i];
    g_off[i] = off;
    g_pos[i] = off;
}

__global__ void build_kernel(int n_edges) {
    int e = blockIdx.x * blockDim.x + threadIdx.x;
    if (e < n_edges) {
        int p = atomicAdd(&g_pos[g_tgt[e]], 1);
        g_csr_src[p] = g_src[e];
    }
}

// ---------------- gather mean-aggregate over fp16 rows (512B contiguous) ---
// 8 neighbors in flight per iteration for deeper MLP.
__global__ void __launch_bounds__(256)
aggregate16_kernel(const __half* __restrict__ feat, int n_nodes,
                   __half* __restrict__ outh) {
    int warp = (blockIdx.x * blockDim.x + threadIdx.x) >> 5;
    int lane = threadIdx.x & 31;
    if (warp >= n_nodes) return;

    int beg = g_off[warp];
    int deg = g_cnt[warp];

    float acc[8] = {0.f, 0.f, 0.f, 0.f, 0.f, 0.f, 0.f, 0.f};
    int i = 0;
    for (; i + 8 <= deg; i += 8) {
        int s0 = __ldg(&g_csr_src[beg + i]);
        int s1 = __ldg(&g_csr_src[beg + i + 1]);
        int s2 = __ldg(&g_csr_src[beg + i + 2]);
        int s3 = __ldg(&g_csr_src[beg + i + 3]);
        int s4 = __ldg(&g_csr_src[beg + i + 4]);
        int s5 = __ldg(&g_csr_src[beg + i + 5]);
        int s6 = __ldg(&g_csr_src[beg + i + 6]);
        int s7 = __ldg(&g_csr_src[beg + i + 7]);
        uint4 v0 = *(const uint4*)(feat + (size_t)s0 * D + lane * 8);
        uint4 v1 = *(const uint4*)(feat + (size_t)s1 * D + lane * 8);
        uint4 v2 = *(const uint4*)(feat + (size_t)s2 * D + lane * 8);
        uint4 v3 = *(const uint4*)(feat + (size_t)s3 * D + lane * 8);
        uint4 v4 = *(const uint4*)(feat + (size_t)s4 * D + lane * 8);
        uint4 v5 = *(const uint4*)(feat + (size_t)s5 * D + lane * 8);
        uint4 v6 = *(const uint4*)(feat + (size_t)s6 * D + lane * 8);
        uint4 v7 = *(const uint4*)(feat + (size_t)s7 * D + lane * 8);
        add8(acc, v0); add8(acc, v1); add8(acc, v2); add8(acc, v3);
        add8(acc, v4); add8(acc, v5); add8(acc, v6); add8(acc, v7);
    }
    for (; i + 2 <= deg; i += 2) {
        int s0 = __ldg(&g_csr_src[beg + i]);
        int s1 = __ldg(&g_csr_src[beg + i + 1]);
        uint4 v0 = *(const uint4*)(feat + (size_t)s0 * D + lane * 8);
        uint4 v1 = *(const uint4*)(feat + (size_t)s1 * D + lane * 8);
        add8(acc, v0); add8(acc, v1);
    }
    if (i < deg) {
        int s0 = __ldg(&g_csr_src[beg + i]);
        uint4 v0 = *(const uint4*)(feat + (size_t)s0 * D + lane * 8);
        add8(acc, v0);
    }

    float iv = 1.0f / (float)(deg > 1 ? deg : 1);
    __half h[8];
    #pragma unroll
    for (int j = 0; j < 8; j++) h[j] = __float2half_rn(acc[j] * iv);

    const int sp = lane >> 1;
    const int kk = (lane & 1) * 8;
    *(uint4*)(outh + ((size_t)sp * NPAD + warp) * 16 + kk) = pack8(h);
}

// ---------------- mma.sync fp16 GEMM (1 pass, fp32 accum, BK=32) -----------
// CTA 128x256, K=512, 16 stages BK=32, 512 thr = 16 warps (4x4), warp 32x64.
// Stage smem: A 128x80B (10240) + B 256x80B (20480) = 30720B, x2 buffers.
#define ROWB   80
#define BOFF0  10240
#define STAGE_B 30720

#define LDSM4(r, addr)                                                      \
    asm volatile("ldmatrix.sync.aligned.m8n8.x4.shared.b16 "                \
                 "{%0,%1,%2,%3}, [%4];"                                     \
                 : "=r"((r)[0]), "=r"((r)[1]), "=r"((r)[2]), "=r"((r)[3])   \
                 : "r"(addr))

#define MMA16(cc, a, b0, b1)                                                \
    asm volatile("mma.sync.aligned.m16n8k16.row.col.f32.f16.f16.f32 "       \
                 "{%0,%1,%2,%3},{%4,%5,%6,%7},{%8,%9},{%0,%1,%2,%3};"       \
                 : "+f"((cc)[0]), "+f"((cc)[1]), "+f"((cc)[2]), "+f"((cc)[3]) \
                 : "r"((a)[0]), "r"((a)[1]), "r"((a)[2]), "r"((a)[3]),      \
                   "r"(b0), "r"(b1))

__global__ void __launch_bounds__(512, 1)
sage_mma_kernel(const __half* __restrict__ inh, const __half* __restrict__ Bw,
                const float* __restrict__ bias, float* __restrict__ outf,
                __half* __restrict__ hh, __half* __restrict__ h16,
                int n_nodes, int do_relu) {
    extern __shared__ __align__(1024) char sm[];
    const uint32_t smb = smem_u32(sm);
    const int tid  = threadIdx.x;
    const int lane = tid & 31;
    const int wid  = tid >> 5;
    const int wm   = wid & 3;
    const int wn   = wid >> 2;
    const int row0 = blockIdx.x * 128;

    // staging: threads 0..255 stage 32B of A; all 512 stage 32B of B
    const bool hasA  = tid < 256;
    const int  rowA  = (tid & 255) >> 1;
    const int  halfA = tid & 1;
    const int  nB    = tid >> 1;           // 0..255
    const int  halfB = tid & 1;
    const uint32_t aDst = rowA * ROWB + halfA * 16u;       // +32 for plane 2s+1
    const uint32_t bDst = BOFF0 + nB * ROWB + halfB * 16u; // +32 for plane 2s+1

    // ldmatrix lane addressing (80B rows; 5r mod 8 -> conflict-free)
    const uint32_t aOff = (uint32_t)(wm * 32 + (lane & 7) + 8 * ((lane >> 3) & 1)) * ROWB
                        + (((uint32_t)lane >> 4) << 4);
    const uint32_t bOff = (uint32_t)(wn * 64 + ((lane >> 4) << 3) + (lane & 7)) * ROWB
                        + ((((uint32_t)lane >> 3) & 1) << 4);

    float c[2][8][4];
    #pragma unroll
    for (int t = 0; t < 2; t++)
        #pragma unroll
        for (int nt = 0; nt < 8; nt++)
            #pragma unroll
            for (int j = 0; j < 4; j++) c[t][nt][j] = 0.f;

    uint4 ra0, ra1, rb0, rb1;
    auto ldg = [&](int s) {                 // s = 0..15, covers k-planes 2s, 2s+1
        const int p0 = 2 * s;
        if (hasA) {
            const __half* srcA = (p0 < 16) ? g_AGh : inh;
            const int pp = p0 & 15;
            const __half* pa = srcA + ((size_t)pp * NPAD + row0 + rowA) * 16
                             + halfA * 8;
            ra0 = *(const uint4*)(pa);
            ra1 = *(const uint4*)(pa + (size_t)NPAD * 16);
        }
        const __half* pb = Bw + p0 * 4096 + nB * 16 + halfB * 8;
        rb0 = *(const uint4*)(pb);
        rb1 = *(const uint4*)(pb + 4096);
    };
    auto sts = [&](int buf) {
        char* bb = sm + buf * STAGE_B;
        if (hasA) {
            *(uint4*)(bb + aDst)      = ra0;
            *(uint4*)(bb + aDst + 32) = ra1;
        }
        *(uint4*)(bb + bDst)      = rb0;
        *(uint4*)(bb + bDst + 32) = rb1;
    };
    auto compute = [&](int buf) {
        const uint32_t bb = smb + buf * STAGE_B;
        #pragma unroll
        for (int ks = 0; ks < 2; ks++) {
            const uint32_t ko = ks * 32;
            uint32_t ah[2][4];
            LDSM4(ah[0], bb + aOff + ko);
            LDSM4(ah[1], bb + aOff + 1280 + ko);
            #pragma unroll
            for (int nt2 = 0; nt2 < 4; nt2++) {
                uint32_t bh[4];
                LDSM4(bh, bb + BOFF0 + bOff + nt2 * 1280 + ko);
                #pragma unroll
                for (int t = 0; t < 2; t++) {
                    MMA16(c[t][nt2 * 2],     ah[t], bh[0], bh[1]);
                    MMA16(c[t][nt2 * 2 + 1], ah[t], bh[2], bh[3]);
                }
            }
        }
    };

    // prologue
    ldg(0);
    sts(0);
    ldg(1);
    __syncthreads();

    #pragma unroll 1
    for (int s = 0; s < 16; s++) {
        compute(s & 1);
        if (s + 1 < 16) {
            sts((s + 1) & 1);          // write buffer not being read
            if (s + 2 < 16) ldg(s + 2);
        }
        __syncthreads();
    }

    // ---- epilogue ----
    #pragma unroll
    for (int t = 0; t < 2; t++) {
        const int r1 = row0 + wm * 32 + t * 16 + (lane >> 2);
        #pragma unroll
        for (int nt = 0; nt < 8; nt++) {
            const int col = wn * 64 + nt * 8 + 2 * (lane & 3);
            float2 b2 = *(const float2*)(bias + col);
            float v0 = c[t][nt][0] + b2.x;
            float v1 = c[t][nt][1] + b2.y;
            float v2 = c[t][nt][2] + b2.x;
            float v3 = c[t][nt][3] + b2.y;
            if (do_relu) {
                v0 = fmaxf(v0, 0.f); v1 = fmaxf(v1, 0.f);
                v2 = fmaxf(v2, 0.f); v3 = fmaxf(v3, 0.f);
            }
            const int sp = col >> 4, kk = col & 15;
            if (r1 < n_nodes) {
                if (outf)
                    *(float2*)(outf + (size_t)r1 * D + col) = make_float2(v0, v1);
                else {
                    uint32_t hi2 =
                        (uint32_t)__half_as_ushort(__float2half_rn(v0)) |
                        ((uint32_t)__half_as_ushort(__float2half_rn(v1)) << 16);
                    *(uint32_t*)(hh + ((size_t)sp * NPAD + r1) * 16 + kk) = hi2;
                    *(uint32_t*)(h16 + (size_t)r1 * D + col) = hi2;
                }
            }
            if (r1 + 8 < n_nodes) {
                if (outf)
                    *(float2*)(outf + (size_t)(r1 + 8) * D + col) = make_float2(v2, v3);
                else {
                    uint32_t hi2 =
                        (uint32_t)__half_as_ushort(__float2half_rn(v2)) |
                        ((uint32_t)__half_as_ushort(__float2half_rn(v3)) << 16);
                    *(uint32_t*)(hh + ((size_t)sp * NPAD + r1 + 8) * 16 + kk) = hi2;
                    *(uint32_t*)(h16 + (size_t)(r1 + 8) * D + col) = hi2;
                }
            }
        }
    }
}

// ---------------- launch ----------------
extern "C" void kernel_launch(void* const* d_in, const int* in_sizes, int n_in,
                              void* d_out, int out_size) {
    const float* x   = (const float*)d_in[0];
    const int*   raw = (const int*)d_in[1];
    const float* W1l = (const float*)d_in[2];
    const float* b1  = (const float*)d_in[3];
    const float* W1r = (const float*)d_in[4];
    const float* W2l = (const float*)d_in[5];
    const float* b2  = (const float*)d_in[6];
    const float* W2r = (const float*)d_in[7];
    float* out = (float*)d_out;

    const int n_nodes = in_sizes[0] / D;
    const int n_edges = in_sizes[1] / 2;

    __half *xh, *hhp, *agh, *bw, *x16, *h16;
    cudaGetSymbolAddress((void**)&xh,  g_Xh);
    cudaGetSymbolAddress((void**)&hhp, g_Hh);
    cudaGetSymbolAddress((void**)&agh, g_AGh);
    cudaGetSymbolAddress((void**)&bw,  g_Bth);
    cudaGetSymbolAddress((void**)&x16, g_X16);
    cudaGetSymbolAddress((void**)&h16, g_H16);

    cudaFuncSetAttribute(sage_mma_kernel,
                         cudaFuncAttributeMaxDynamicSharedMemorySize,
                         2 * STAGE_B);

    const int mma_blocks  = (n_nodes + 127) / 128;
    const int agg_blocks  = (n_nodes * 32 + 255) / 256;
    const int eb = (n_edges + 255) / 256;
    const int nb = (n_nodes + 255) / 256;
    const int scan_blocks = (n_nodes + 255) / 256;
    const int wb = (2 * 256 * 512 + 255) / 256;
    const int cb = (n_nodes * 64 + 255) / 256;
    const int smem = 2 * STAGE_B;

    // ---- fused prologue (zero+detect | convert_x | prep_w) ----
    prologue_kernel<<<nb + cb + wb, 256>>>(n_nodes, raw, n_edges, x,
                                           W1l, W1r, W2l, W2r, nb, cb);

    // ---- decode + CSR build ----
    extract_count_kernel<<<eb, 256>>>(raw, n_edges, n_nodes);
    scan_a_kernel<<<scan_blocks, 256>>>(n_nodes);
    scan_b_kernel<<<1, 256>>>(scan_blocks);
    scan_c_kernel<<<scan_blocks, 256>>>(n_nodes);
    build_kernel<<<eb, 256>>>(n_edges);

    // ---- layer 1 ----
    aggregate16_kernel<<<agg_blocks, 256>>>(x16, n_nodes, agh);
    sage_mma_kernel<<<mma_blocks, 512, smem>>>(xh, bw, b1, nullptr,
                                               hhp, h16, n_nodes, 1);

    // ---- layer 2 ----
    aggregate16_kernel<<<agg_blocks, 256>>>(h16, n_nodes, agh);
    sage_mma_kernel<<<mma_blocks, 512, smem>>>(hhp, bw + 256 * 512, b2, out,
                                               nullptr, nullptr, n_nodes, 0);
}